// round 6
// baseline (speedup 1.0000x reference)
#include <cuda_runtime.h>
#include <cuda_bf16.h>
#include <cstdint>

// LongformerAttention_44315472560501
// output            = hidden_states  (identity copy, 32 MiB f32)
// attention_weights = zeros          (128 MiB f32)
//
// R6: 3-way parallel graph branches.
//   branch A (side stream 1): D2D memcpy of the 32 MiB identity copy
//   branch B (main stream)  : memset of the first half of the zero region
//   branch C (side stream 2): memset of the second half of the zero region
// Splitting the 160 MiB memset lets the two halves' kernel waves ramp
// concurrently and overlap the CE copy. R5 (2-way fork) = 34.8us; honest
// DRAM floor for 235 MB of traffic ~= 33.5us at ~7 TB/s.
//
// Host-side stream/event objects are created lazily on the first
// (non-captured) correctness call; no device memory is ever allocated.
// Falls back to the proven serial R3 path on any creation failure.

static cudaStream_t g_s1 = nullptr;   // copy branch
static cudaStream_t g_s2 = nullptr;   // memset half 2 branch
static cudaEvent_t  g_fork  = nullptr;
static cudaEvent_t  g_join1 = nullptr;
static cudaEvent_t  g_join2 = nullptr;
static int          g_ready = 0;      // 0=uninit, 1=ok, -1=failed

extern "C" void kernel_launch(void* const* d_in, const int* in_sizes, int n_in,
                              void* d_out, int out_size)
{
    const float* hidden = (const float*)d_in[0];
    float* out = (float*)d_out;

    long long n_total = (long long)out_size;
    long long n_copy  = (long long)in_sizes[0];
    if (n_copy > n_total) n_copy = n_total;
    long long n_zero = n_total - n_copy;

    if (g_ready == 0) {
        if (cudaStreamCreateWithFlags(&g_s1, cudaStreamNonBlocking) == cudaSuccess &&
            cudaStreamCreateWithFlags(&g_s2, cudaStreamNonBlocking) == cudaSuccess &&
            cudaEventCreateWithFlags(&g_fork,  cudaEventDisableTiming) == cudaSuccess &&
            cudaEventCreateWithFlags(&g_join1, cudaEventDisableTiming) == cudaSuccess &&
            cudaEventCreateWithFlags(&g_join2, cudaEventDisableTiming) == cudaSuccess) {
            g_ready = 1;
        } else {
            g_ready = -1;
        }
    }

    if (g_ready == 1 && n_copy > 0 && n_zero > 0) {
        // split zero region into two ~equal halves, 256B-aligned split point
        long long half = (n_zero / 2) & ~63LL;   // multiple of 64 floats = 256B
        if (half <= 0) half = n_zero;            // tiny region: one piece
        long long rest = n_zero - half;

        // fork
        cudaEventRecord(g_fork, 0);
        cudaStreamWaitEvent(g_s1, g_fork, 0);

        // branch A: identity copy (copy engine / separate queue)
        cudaMemcpyAsync(out, hidden, (size_t)n_copy * sizeof(float),
                        cudaMemcpyDeviceToDevice, g_s1);
        cudaEventRecord(g_join1, g_s1);

        // branch C: second memset half
        if (rest > 0) {
            cudaStreamWaitEvent(g_s2, g_fork, 0);
            cudaMemsetAsync(out + n_copy + half, 0,
                            (size_t)rest * sizeof(float), g_s2);
            cudaEventRecord(g_join2, g_s2);
        }

        // branch B: first memset half on the capture stream
        cudaMemsetAsync(out + n_copy, 0, (size_t)half * sizeof(float), 0);

        // join
        cudaStreamWaitEvent(0, g_join1, 0);
        if (rest > 0) cudaStreamWaitEvent(0, g_join2, 0);
    } else {
        // serial fallback (proven R3 path)
        if (n_copy > 0) {
            cudaMemcpyAsync(out, hidden, (size_t)n_copy * sizeof(float),
                            cudaMemcpyDeviceToDevice, 0);
        }
        if (n_zero > 0) {
            cudaMemsetAsync(out + n_copy, 0, (size_t)n_zero * sizeof(float), 0);
        }
    }
}

// round 9
// speedup vs baseline: 1.0018x; 1.0018x over previous
#include <cuda_runtime.h>
#include <cuda_bf16.h>
#include <cstdint>

// LongformerAttention_44315472560501
// output            = hidden_states  (identity copy, 32 MiB f32)
// attention_weights = zeros          (128 MiB f32)
//
// R9: byte-identical revert to the R5 record holder (34.8us). R7/R8's
// slice-balancing variant hit back-to-back container failures and its
// predicted upside was within noise; locking in the proven best.
//
// Structure: parallel-branch graph. Fork the D2D memcpy onto a secondary
// stream (event fork/join) so it overlaps the big memsetAsync.
// Roofline: 235 MB mandatory traffic at ~6.75-7 TB/s effective => ~33.5us
// floor; this kernel delivers 34.8us end-to-end (~96% of achievable).
//
// No device memory is allocated: only a stream + 2 events, created once on
// the first (non-captured) correctness call. Falls back to the proven serial
// R3 path if creation fails.

static cudaStream_t g_side = nullptr;
static cudaEvent_t  g_fork = nullptr;
static cudaEvent_t  g_join = nullptr;
static int          g_ready = 0;   // 0=uninit, 1=ok, -1=failed

extern "C" void kernel_launch(void* const* d_in, const int* in_sizes, int n_in,
                              void* d_out, int out_size)
{
    const float* hidden = (const float*)d_in[0];
    float* out = (float*)d_out;

    long long n_total = (long long)out_size;
    long long n_copy  = (long long)in_sizes[0];
    if (n_copy > n_total) n_copy = n_total;
    long long n_zero = n_total - n_copy;

    if (g_ready == 0) {
        // one-time resource creation (host-side objects only; happens on the
        // non-captured correctness call, never re-run during capture/replay)
        if (cudaStreamCreateWithFlags(&g_side, cudaStreamNonBlocking) == cudaSuccess &&
            cudaEventCreateWithFlags(&g_fork, cudaEventDisableTiming) == cudaSuccess &&
            cudaEventCreateWithFlags(&g_join, cudaEventDisableTiming) == cudaSuccess) {
            g_ready = 1;
        } else {
            g_ready = -1;
        }
    }

    if (g_ready == 1 && n_copy > 0 && n_zero > 0) {
        // fork: copy branch on side stream, memset on main (capture) stream
        cudaEventRecord(g_fork, 0);
        cudaStreamWaitEvent(g_side, g_fork, 0);

        cudaMemcpyAsync(out, hidden, (size_t)n_copy * sizeof(float),
                        cudaMemcpyDeviceToDevice, g_side);
        cudaEventRecord(g_join, g_side);

        cudaMemsetAsync(out + n_copy, 0, (size_t)n_zero * sizeof(float), 0);

        // join: main stream waits for the copy branch
        cudaStreamWaitEvent(0, g_join, 0);
    } else {
        // serial fallback (proven R3 path)
        if (n_copy > 0) {
            cudaMemcpyAsync(out, hidden, (size_t)n_copy * sizeof(float),
                            cudaMemcpyDeviceToDevice, 0);
        }
        if (n_zero > 0) {
            cudaMemsetAsync(out + n_copy, 0, (size_t)n_zero * sizeof(float), 0);
        }
    }
}